// round 15
// baseline (speedup 1.0000x reference)
#include <cuda_runtime.h>
#include <cuda_fp16.h>
#include <stdint.h>

// ---------------- problem constants ----------------
#define NB   128
#define RNUM 300
#define EMB  32

// ---------------- buffers ----------------
// grid: half NHWC [n][76][76][40]: ch0-31 = emb, ch32 = occupancy, 33-39 pad
__device__ unsigned g_grid[NB * 76 * 76 * 20];   // half2 words
__device__ unsigned g_c1 [NB * 72 * 72 * 32];    // conv1 out half2 (64ch)
__device__ unsigned g_p1 [NB * 37 * 37 * 32];    // pool1 half2 (pad1)
__device__ unsigned g_c2 [NB * 35 * 35 * 64];    // conv2 out half2 (128ch)
__device__ unsigned g_p2 [NB * 19 * 19 * 64];    // pool2 half2 (pad1)
__device__ float    g_gap[NB * 256];
__device__ float    g_f1 [NB * 512];
__device__ float    g_f2 [NB * 256];
// conv1 B: emb [tap25][c16 2][nt8][64] + occ [g2][nt8][64]
__device__ unsigned g_wt1[ 26624];
__device__ unsigned g_wt2[ 36864];               // [cob2][tap9][c16 4][nt8][64]
__device__ unsigned g_wt3[147456];               // [h2][cob4][kk9][c16 4][nt8][64]

// ---------------- helpers ----------------
__device__ __forceinline__ void mma_f16(float* d, const uint32_t* a, const uint32_t* b) {
    asm volatile(
        "mma.sync.aligned.m16n8k16.row.col.f32.f16.f16.f32 "
        "{%0,%1,%2,%3}, {%4,%5,%6,%7}, {%8,%9}, {%0,%1,%2,%3};"
        : "+f"(d[0]), "+f"(d[1]), "+f"(d[2]), "+f"(d[3])
        : "r"(a[0]), "r"(a[1]), "r"(a[2]), "r"(a[3]), "r"(b[0]), "r"(b[1]));
}
__device__ __forceinline__ void ldsm_x4(uint32_t* a, uint32_t addr) {
    asm volatile("ldmatrix.sync.aligned.m8n8.x4.shared.b16 {%0,%1,%2,%3}, [%4];"
        : "=r"(a[0]), "=r"(a[1]), "=r"(a[2]), "=r"(a[3]) : "r"(addr));
}
__device__ __forceinline__ uint32_t smem_u32(const void* p) {
    uint32_t a;
    asm("{ .reg .u64 t; cvta.to.shared.u64 t, %1; cvt.u32.u64 %0, t; }" : "=r"(a) : "l"(p));
    return a;
}
__device__ __forceinline__ void cp_async16_s(uint32_t saddr, const void* g) {
    asm volatile("cp.async.cg.shared.global [%0], [%1], 16;" :: "r"(saddr), "l"(g));
}
__device__ __forceinline__ void cp_async16_z(uint32_t saddr, const void* g, uint32_t srcsz) {
    asm volatile("cp.async.cg.shared.global [%0], [%1], 16, %2;"
                 :: "r"(saddr), "l"(g), "r"(srcsz));
}
__device__ __forceinline__ uint32_t f2h2(float a, float b) {
    __half2 h = __float22half2_rn(make_float2(a, b));
    return *(uint32_t*)&h;
}

// ---------------- zero fill ----------------
__global__ void zero_kernel(float4* __restrict__ p, int n4) {
    int i = blockIdx.x * blockDim.x + threadIdx.x;
    if (i < n4) p[i] = make_float4(0.f, 0.f, 0.f, 0.f);
}

// ---------------- scatter rooms into half grid (half2 atomics) --------------
__global__ void scatter_kernel(const int* __restrict__ X,
                               const int* __restrict__ rm,
                               const float* __restrict__ emb,
                               __half2* __restrict__ grid) {
    int idx = blockIdx.x * blockDim.x + threadIdx.x;
    if (idx >= NB * RNUM * 64) return;
    int cell = idx & 63;
    int r    = (idx >> 6) % RNUM;
    int n    = idx / (RNUM * 64);
    if (!rm[r * 64 + cell]) return;
    int cx = cell >> 3, cy = cell & 7;
    int px = X[(n * RNUM + r) * 2 + 0];
    int py = X[(n * RNUM + r) * 2 + 1];
    int Y = py + cy + 2, Xc = px + cx + 2;
    __half2* base = grid + (((size_t)n * 76 + Y) * 76 + Xc) * 20;
    const float* er = emb + r * EMB;
#pragma unroll
    for (int w = 0; w < 16; ++w)
        atomicAdd(base + w, __float22half2_rn(make_float2(er[2 * w], er[2 * w + 1])));
    atomicAdd(base + 16, __float22half2_rn(make_float2(1.f, 0.f)));
}

// ------- fused weight transform (all three convs, one launch) ---------------
__global__ void wtrans_all_kernel(const float* __restrict__ w0,
                                  const float* __restrict__ w1,
                                  const float* __restrict__ w2,
                                  unsigned* __restrict__ wt1,
                                  unsigned* __restrict__ wt2,
                                  unsigned* __restrict__ wt3) {
    int i = blockIdx.x * blockDim.x + threadIdx.x;
    if (i < 26624) {
        // conv1: emb [tap25][c16 2][nt8][64] + occ [g2][nt8][64]
        int which = i & 1;
        int lane  = (i >> 1) & 31;
        int ac = lane & 3, ar = lane >> 2;
        if (i < 25600) {
            int r  = i >> 6;
            int nt = r % 8;  r /= 8;
            int c16 = r % 2;
            int tap = r / 2;
            int kl  = c16 * 16 + ac * 2 + which * 8;
            int co  = nt * 8 + ar;
            float v0 = w0[((size_t)co * 33 + 1 + kl) * 25 + tap];
            float v1 = w0[((size_t)co * 33 + 2 + kl) * 25 + tap];
            wt1[i] = f2h2(v0, v1);
        } else {
            int j  = i - 25600;
            int r2 = j >> 6;
            int nt = r2 % 8;
            int g  = r2 / 8;
            int kl = g * 16 + ac * 2 + which * 8;
            int co = nt * 8 + ar;
            float v0 = (kl     < 25) ? w0[((size_t)co * 33) * 25 + kl]     : 0.f;
            float v1 = (kl + 1 < 25) ? w0[((size_t)co * 33) * 25 + kl + 1] : 0.f;
            wt1[i] = f2h2(v0, v1);
        }
    } else if (i < 26624 + 36864) {
        // conv2: [cob2][kk9][c16 4][nt8][64]
        int j = i - 26624;
        int which = j & 1;
        int lane  = (j >> 1) & 31;
        int r     = j >> 6;
        int nt  = r % 8;  r /= 8;
        int c16 = r % 4;  r /= 4;
        int kk  = r % 9;
        int cob = r / 9;
        int ac = lane & 3, ar = lane >> 2;
        int ci0 = c16 * 16 + ac * 2 + which * 8;
        int co  = cob * 64 + nt * 8 + ar;
        float v0 = w1[((size_t)co * 64 + ci0)     * 9 + kk];
        float v1 = w1[((size_t)co * 64 + ci0 + 1) * 9 + kk];
        wt2[j] = f2h2(v0, v1);
    } else if (i < 26624 + 36864 + 147456) {
        // conv3: [h2][cob4][kk9][c16 4][nt8][64]
        int j = i - 26624 - 36864;
        int which = j & 1;
        int lane  = (j >> 1) & 31;
        int r     = j >> 6;
        int nt  = r % 8;  r /= 8;
        int c16 = r % 4;  r /= 4;
        int kk  = r % 9;  r /= 9;
        int cob = r % 4;
        int h   = r / 4;
        int ac = lane & 3, ar = lane >> 2;
        int ci0 = h * 64 + c16 * 16 + ac * 2 + which * 8;
        int co  = cob * 64 + nt * 8 + ar;
        float v0 = w2[((size_t)co * 128 + ci0)     * 9 + kk];
        float v1 = w2[((size_t)co * 128 + ci0 + 1) * 9 + kk];
        wt3[j] = f2h2(v0, v1);
    }
}

// ---------------- conv1: NCO=64, MT=4, NT=8, 256thr (measured best) ----------
__global__ void __launch_bounds__(256, 1)
conv1_kernel(const unsigned* __restrict__ in, const unsigned* __restrict__ wt,
             const float* __restrict__ bias, unsigned* __restrict__ out) {
    constexpr int MT = 4, NT = 8, NTHR = 256;
    constexpr int MPIX = 512;
    constexpr int W = 72, PAD = 2, Wp = 76, NPIX = 76 * 76;
    constexpr int HALO = PAD * Wp + PAD;              // 154
    constexpr int AWIN = MPIX + 2 * HALO;             // 820
    constexpr int ASTE = 20;
    constexpr int AEW  = AWIN * ASTE;                 // 16400
    constexpr int IMW  = MPIX * ASTE;                 // 10240
    constexpr int OCW  = 416;
    constexpr int BW   = 26624;

    extern __shared__ uint32_t sm[];
    uint32_t* sAe = sm;
    uint32_t* sIm = sm + AEW;
    __half*   sOc = (__half*)(sm + AEW + IMW);
    uint32_t* sB  = sm + AEW + IMW + OCW;

    const int tid  = threadIdx.x;
    const int warp = tid >> 5, lane = tid & 31;
    const int ar   = lane >> 2, ac = lane & 3;
    const int n    = blockIdx.z;
    const int p0   = HALO + blockIdx.x * MPIX;
    const int s0   = p0 - HALO;
    const int wrow = warp * (16 * MT);

    {
        uint32_t sBu = smem_u32(sB);
        for (int c = tid; c < BW / 4; c += NTHR)
            cp_async16_s(sBu + c * 16, wt + c * 4);
        const unsigned* inb = in + (size_t)n * NPIX * 20;
        uint32_t sAu = smem_u32(sAe);
        for (int e = tid; e < AWIN * 4; e += NTHR) {
            int row = e >> 2, c = e & 3;
            int pix = s0 + row;
            cp_async16_z(sAu + (uint32_t)((row * ASTE + c * 4) * 4),
                         inb + (size_t)pix * 20 + c * 4,
                         (pix < NPIX) ? 16u : 0u);
        }
        asm volatile("cp.async.commit_group;" ::: "memory");
    }
    {
        const unsigned* inw = in + (size_t)n * NPIX * 20;
        for (int row = tid; row < AWIN; row += NTHR) {
            int pix = s0 + row;
            uint32_t v = (pix < NPIX) ? inw[(size_t)pix * 20 + 16] : 0u;
            sOc[row] = *(__half*)&v;
        }
    }
    __syncthreads();
    {
        __half* imh = (__half*)sIm;
        for (int e = tid; e < MPIX * 16; e += NTHR) {
            int rr = e >> 4, w2 = e & 15;
            int k0 = 2 * w2, k1 = 2 * w2 + 1;
            __half h0 = __float2half(0.f), h1 = h0;
            if (k0 < 25) {
                int sh = (k0 / 5 - 2) * Wp + (k0 % 5) - 2;
                h0 = sOc[rr + HALO + sh];
            }
            if (k1 < 25) {
                int sh = (k1 / 5 - 2) * Wp + (k1 % 5) - 2;
                h1 = sOc[rr + HALO + sh];
            }
            imh[(rr * ASTE) * 2 + 2 * w2]     = h0;
            imh[(rr * ASTE) * 2 + 2 * w2 + 1] = h1;
        }
    }
    asm volatile("cp.async.wait_group 0;" ::: "memory");
    __syncthreads();

    float d[MT][NT][4];
#pragma unroll
    for (int mt = 0; mt < MT; ++mt)
#pragma unroll
        for (int nt = 0; nt < NT; ++nt)
#pragma unroll
            for (int q = 0; q < 4; ++q) d[mt][nt][q] = 0.f;

    const uint32_t a_off0 = smem_u32(sAe) +
        (uint32_t)(((HALO + wrow + (lane & 15)) * ASTE + ((lane >> 4) << 2)) * 4);
    const uint32_t i_off0 = smem_u32(sIm) +
        (uint32_t)(((wrow + (lane & 15)) * ASTE + ((lane >> 4) << 2)) * 4);

    for (int tap = 0; tap < 25; ++tap) {
        int shift = (tap / 5 - PAD) * Wp + (tap % 5) - PAD;
        uint32_t abase = a_off0 + (uint32_t)(shift * (ASTE * 4));
        const uint2* btap = (const uint2*)sB + (size_t)tap * 512 + lane;
#pragma unroll
        for (int c16 = 0; c16 < 2; ++c16) {
            uint2 bf[NT];
#pragma unroll
            for (int nt = 0; nt < NT; ++nt)
                bf[nt] = btap[(c16 * NT + nt) * 32];
#pragma unroll
            for (int mt = 0; mt < MT; ++mt) {
                uint32_t af[4];
                ldsm_x4(af, abase + (uint32_t)((mt * 16 * ASTE + c16 * 8) * 4));
#pragma unroll
                for (int nt = 0; nt < NT; ++nt)
                    mma_f16(d[mt][nt], af, (const uint32_t*)&bf[nt]);
            }
        }
    }
    {
        const uint2* btap = (const uint2*)(sB + 25600) + lane;
#pragma unroll
        for (int g = 0; g < 2; ++g) {
            uint2 bf[NT];
#pragma unroll
            for (int nt = 0; nt < NT; ++nt)
                bf[nt] = btap[(g * NT + nt) * 32];
#pragma unroll
            for (int mt = 0; mt < MT; ++mt) {
                uint32_t af[4];
                ldsm_x4(af, i_off0 + (uint32_t)((mt * 16 * ASTE + g * 8) * 4));
#pragma unroll
                for (int nt = 0; nt < NT; ++nt)
                    mma_f16(d[mt][nt], af, (const uint32_t*)&bf[nt]);
            }
        }
    }

    float2 bv[NT];
#pragma unroll
    for (int nt = 0; nt < NT; ++nt)
        bv[nt] = *(const float2*)(bias + nt * 8 + 2 * ac);
#pragma unroll
    for (int mt = 0; mt < MT; ++mt) {
#pragma unroll
        for (int half = 0; half < 2; ++half) {
            int p = p0 + wrow + mt * 16 + half * 8 + ar;
            int y = p / Wp - PAD, x = p % Wp - PAD;
            // pool1 reads rows/cols 0..70 only — skip dead row/col 71
            if (x >= 0 && x < 71 && y >= 0 && y < 71) {
                uint32_t* ob = out + (((size_t)n * W + y) * W + x) * 32 + ac;
#pragma unroll
                for (int nt = 0; nt < NT; ++nt) {
                    float vx = fmaxf(d[mt][nt][half * 2 + 0] + bv[nt].x, 0.f);
                    float vy = fmaxf(d[mt][nt][half * 2 + 1] + bv[nt].y, 0.f);
                    ob[nt * 4] = f2h2(vx, vy);
                }
            }
        }
    }
}

// ------ conv2: batch-flattened M, MT=2 NT=8, per-tap B stream, 2 blk/SM ------
__global__ void __launch_bounds__(256, 2)
conv2_kernel(const unsigned* __restrict__ in, const unsigned* __restrict__ wt,
             const float* __restrict__ bias, unsigned* __restrict__ out) {
    constexpr int NT = 8, MT = 2, NTHR = 256;
    constexpr int K = 3, H = 35, W = 35, PAD = 1;
    constexpr int CO_TOTAL = 128;
    constexpr int NC16 = 4, TAPS = 9;
    constexpr int MPIX = 256;
    constexpr int Wp = 37, IMG = 37 * 37;            // 1369
    constexpr int TOT = NB * IMG;                    // 175232
    constexpr int HALO = PAD * Wp + PAD;             // 38
    constexpr int AWIN = MPIX + 2 * HALO;            // 332
    constexpr int AST2 = 36;
    constexpr int AWORDS = AWIN * AST2;
    constexpr int BSLOT = NC16 * NT * 64;            // 2048

    extern __shared__ uint32_t sm[];
    uint32_t* sA = sm;
    uint32_t* sB = sm + AWORDS;

    const int tid  = threadIdx.x;
    const int warp = tid >> 5, lane = tid & 31;
    const int ar   = lane >> 2, ac = lane & 3;
    const int cob  = blockIdx.y;
    const int co0  = cob * 64;
    const int p0   = HALO + blockIdx.x * MPIX;
    const int s0   = p0 - HALO;
    const int wrow = warp * (16 * MT);

    const unsigned* wtc = wt + (size_t)cob * (TAPS * BSLOT);
    const uint32_t sBu = smem_u32(sB);
#pragma unroll
    for (int pf = 0; pf < 2; ++pf) {
        const unsigned* src = wtc + (size_t)pf * BSLOT;
        for (int c = tid; c < BSLOT / 4; c += NTHR)
            cp_async16_s(sBu + (pf * BSLOT + c * 4) * 4, src + c * 4);
        asm volatile("cp.async.commit_group;" ::: "memory");
    }
    {
        const uint4* inb = (const uint4*)in;
        uint32_t sAu = smem_u32(sA);
        for (int e = tid; e < AWIN * 8; e += NTHR) {
            int row = e >> 3, c = e & 7;
            int pix = s0 + row;
            cp_async16_z(sAu + (uint32_t)((row * AST2 + c * 4) * 4),
                         inb + (size_t)pix * 8 + c,
                         (pix < TOT) ? 16u : 0u);
        }
        asm volatile("cp.async.commit_group;" ::: "memory");
    }
    asm volatile("cp.async.wait_group 0;" ::: "memory");
    __syncthreads();

    float d[MT][NT][4];
#pragma unroll
    for (int mt = 0; mt < MT; ++mt)
#pragma unroll
        for (int nt = 0; nt < NT; ++nt)
#pragma unroll
            for (int q = 0; q < 4; ++q) d[mt][nt][q] = 0.f;

    const uint32_t a_off0 = smem_u32(sA) +
        (uint32_t)(((HALO + wrow + (lane & 15)) * AST2 + ((lane >> 4) << 2)) * 4);

#pragma unroll 1
    for (int tap = 0; tap < TAPS; ++tap) {
        if (tap >= 2) {
            asm volatile("cp.async.wait_group 1;" ::: "memory");
            __syncthreads();
        }
        int shift = (tap / K - PAD) * Wp + (tap % K) - PAD;
        uint32_t abase = a_off0 + (uint32_t)(shift * (AST2 * 4));
        const uint2* btap = (const uint2*)(sB + (tap & 1) * BSLOT) + lane;
#pragma unroll
        for (int c16 = 0; c16 < NC16; ++c16) {
            uint2 bf[NT];
#pragma unroll
            for (int nt = 0; nt < NT; ++nt)
                bf[nt] = btap[(c16 * NT + nt) * 32];
#pragma unroll
            for (int mt = 0; mt < MT; ++mt) {
                uint32_t af[4];
                ldsm_x4(af, abase + (uint32_t)((mt * 16 * AST2 + c16 * 8) * 4));
#pragma unroll
                for (int nt = 0; nt < NT; ++nt)
                    mma_f16(d[mt][nt], af, (const uint32_t*)&bf[nt]);
            }
        }
        if (tap + 2 < TAPS) {
            __syncthreads();
            const unsigned* src = wtc + (size_t)(tap + 2) * BSLOT;
            uint32_t dst = sBu + (tap & 1) * BSLOT * 4;
            for (int c = tid; c < BSLOT / 4; c += NTHR)
                cp_async16_s(dst + c * 16, src + c * 4);
            asm volatile("cp.async.commit_group;" ::: "memory");
        }
    }

    float2 bv[NT];
#pragma unroll
    for (int nt = 0; nt < NT; ++nt)
        bv[nt] = *(const float2*)(bias + co0 + nt * 8 + 2 * ac);

#pragma unroll
    for (int mt = 0; mt < MT; ++mt) {
#pragma unroll
        for (int half = 0; half < 2; ++half) {
            int p = p0 + wrow + mt * 16 + half * 8 + ar;
            if (p < TOT) {
                int n = p / IMG, l = p % IMG;
                int y = l / Wp - PAD, x = l % Wp - PAD;
                if (x >= 0 && x < W && y >= 0 && y < H) {
                    size_t pix = ((size_t)n * H + y) * W + x;
                    uint32_t* ob = (uint32_t*)out + pix * (CO_TOTAL / 2) + co0 / 2 + ac;
#pragma unroll
                    for (int nt = 0; nt < NT; ++nt) {
                        float vx = fmaxf(d[mt][nt][half * 2 + 0] + bv[nt].x, 0.f);
                        float vy = fmaxf(d[mt][nt][half * 2 + 1] + bv[nt].y, 0.f);
                        ob[nt * 4] = f2h2(vx, vy);
                    }
                }
            }
        }
    }
}

// ------- conv3 fused: both ci halves (B restage) + bias/relu + pool3 + GAP ----
__global__ void __launch_bounds__(256, 1)
conv3_kernel(const unsigned* __restrict__ in, const unsigned* __restrict__ wt,
             const float* __restrict__ bias, float* __restrict__ gap) {
    constexpr int NT = 8, MT = 3;
    constexpr int K = 3, H = 17, W = 17, PAD = 1;
    constexpr int NC16 = 4, TAPS = 9;
    constexpr int MPIX = 8 * 16 * MT;                 // 384
    constexpr int Wp = W + 2 * PAD, Hp = H + 2 * PAD;
    constexpr int NPIX = Wp * Hp;                     // 361
    constexpr int HALO = PAD * Wp + PAD;              // 20
    constexpr int AWIN = MPIX + 2 * HALO;             // 424
    constexpr int AST2 = 36;
    constexpr int AWORDS = 2 * AWIN * AST2;           // 30528
    constexpr int BWORDS = TAPS * NC16 * NT * 64;     // 18432
    constexpr int OST = 65;

    extern __shared__ uint32_t sm[];
    uint32_t* sA = sm;
    uint32_t* sB = sm + AWORDS;
    float*    sOut  = (float*)sm;
    float*    sPart = (float*)(sm + AWORDS);

    const int tid  = threadIdx.x;
    const int warp = tid >> 5, lane = tid & 31;
    const int ar   = lane >> 2, ac = lane & 3;
    const int n    = blockIdx.z;
    const int cob  = blockIdx.y;
    const int co0  = cob * 64;
    const int p0   = HALO;
    const int wrow = warp * (16 * MT);

    {
        const unsigned* wsrc = wt + (size_t)cob * BWORDS;
        uint32_t sBu = smem_u32(sB);
        for (int c = tid; c < BWORDS / 4; c += 256)
            cp_async16_s(sBu + c * 16, wsrc + c * 4);
        const uint4* inb = (const uint4*)in + (size_t)n * NPIX * 16;
        uint32_t sAu = smem_u32(sA);
        for (int e = tid; e < 2 * AWIN * 8; e += 256) {
            int h   = e / (AWIN * 8);
            int r2  = e % (AWIN * 8);
            int row = r2 >> 3, c = r2 & 7;
            cp_async16_z(sAu + (uint32_t)(((h * AWIN + row) * AST2 + c * 4) * 4),
                         inb + (size_t)row * 16 + h * 8 + c,
                         (row < NPIX) ? 16u : 0u);
        }
        asm volatile("cp.async.commit_group;" ::: "memory");
    }
    asm volatile("cp.async.wait_group 0;" ::: "memory");
    __syncthreads();

    float d[MT][NT][4];
#pragma unroll
    for (int mt = 0; mt < MT; ++mt)
#pragma unroll
        for (int nt = 0; nt < NT; ++nt)
#pragma unroll
            for (int q = 0; q < 4; ++q) d[mt][nt][q] = 0.f;

    const uint32_t a_off0 = smem_u32(sA) +
        (uint32_t)(((HALO + wrow + (lane & 15)) * AST2 + ((lane >> 4) << 2)) * 4);

#pragma unroll 1
    for (int h = 0; h < 2; ++h) {
        if (h == 1) {
            __syncthreads();
            const unsigned* wsrc = wt + ((size_t)4 + cob) * BWORDS;
            uint32_t sBu = smem_u32(sB);
            for (int c = tid; c < BWORDS / 4; c += 256)
                cp_async16_s(sBu + c * 16, wsrc + c * 4);
            asm volatile("cp.async.commit_group;" ::: "memory");
            asm volatile("cp.async.wait_group 0;" ::: "memory");
            __syncthreads();
        }
        uint32_t a_h = a_off0 + (uint32_t)(h * AWIN * AST2 * 4);
        for (int tap = 0; tap < TAPS; ++tap) {
            int shift = (tap / K - PAD) * Wp + (tap % K) - PAD;
            uint32_t abase = a_h + (uint32_t)(shift * (AST2 * 4));
            const uint2* btap = (const uint2*)sB + (size_t)tap * (NC16 * NT * 32) + lane;
#pragma unroll
            for (int c16 = 0; c16 < NC16; ++c16) {
                uint2 bf[NT];
#pragma unroll
                for (int nt = 0; nt < NT; ++nt)
                    bf[nt] = btap[(c16 * NT + nt) * 32];
#pragma unroll
                for (int mt = 0; mt < MT; ++mt) {
                    uint32_t af[4];
                    ldsm_x4(af, abase + (uint32_t)((mt * 16 * AST2 + c16 * 8) * 4));
#pragma unroll
                    for (int nt = 0; nt < NT; ++nt)
                        mma_f16(d[mt][nt], af, (const uint32_t*)&bf[nt]);
                }
            }
        }
    }

    float2 bv[NT];
#pragma unroll
    for (int nt = 0; nt < NT; ++nt)
        bv[nt] = *(const float2*)(bias + co0 + nt * 8 + 2 * ac);

    __syncthreads();

#pragma unroll
    for (int mt = 0; mt < MT; ++mt) {
#pragma unroll
        for (int half = 0; half < 2; ++half) {
            int p = p0 + wrow + mt * 16 + half * 8 + ar;
            int y = p / Wp - PAD, x = p % Wp - PAD;
            if (x >= 0 && x < W && y < H) {
                float* so = sOut + (y * W + x) * OST + 2 * ac;
#pragma unroll
                for (int nt = 0; nt < NT; ++nt) {
                    so[nt * 8 + 0] = fmaxf(d[mt][nt][half * 2 + 0] + bv[nt].x, 0.f);
                    so[nt * 8 + 1] = fmaxf(d[mt][nt][half * 2 + 1] + bv[nt].y, 0.f);
                }
            }
        }
    }
    __syncthreads();

    {
        int c = tid >> 2, seg = tid & 3;
        float s = 0.f;
#pragma unroll
        for (int j = 0; j < 16; ++j) {
            int pp = seg * 16 + j;
            int oy = pp >> 3, ox = pp & 7;
            const float* b0 = sOut + ((2 * oy) * W + 2 * ox) * OST + c;
            float m = b0[0];
#pragma unroll
            for (int dy = 0; dy < 3; ++dy)
#pragma unroll
                for (int dx = 0; dx < 3; ++dx)
                    m = fmaxf(m, b0[(dy * W + dx) * OST]);
            s += m;
        }
        sPart[c * 4 + seg] = s;
    }
    __syncthreads();
    if (tid < 64) {
        float s = sPart[tid * 4] + sPart[tid * 4 + 1] + sPart[tid * 4 + 2] + sPart[tid * 4 + 3];
        gap[(size_t)n * 256 + co0 + tid] = s * (1.0f / 64.0f);
    }
}

// ---------------- pools (write own pad frame) / fc ----------------
template<int C, int HI, int HO, int P>
__global__ void pool_half_kernel(const uint2* __restrict__ in, uint2* __restrict__ out) {
    constexpr int C4 = C / 4, HOP = HO + 2 * P;
    int idx = blockIdx.x * blockDim.x + threadIdx.x;
    if (idx >= NB * HOP * HOP * C4) return;
    int c  = idx % C4;
    int ox = (idx / C4) % HOP;
    int oy = (idx / (C4 * HOP)) % HOP;
    int n  = idx / (C4 * HOP * HOP);
    uint2 r;
    if (ox < P || ox >= HO + P || oy < P || oy >= HO + P) {
        r = make_uint2(0u, 0u);
    } else {
        const uint2* p = in + (((size_t)n * HI + 2 * (oy - P)) * HI + 2 * (ox - P)) * C4 + c;
        uint2 m0 = p[0];
        __half2 ma = *(__half2*)&m0.x, mb = *(__half2*)&m0.y;
#pragma unroll
        for (int dy = 0; dy < 3; ++dy)
#pragma unroll
            for (int dx = 0; dx < 3; ++dx) {
                uint2 q = p[((size_t)dy * HI + dx) * C4];
                ma = __hmax2(ma, *(__half2*)&q.x);
                mb = __hmax2(mb, *(__half2*)&q.y);
            }
        r.x = *(uint32_t*)&ma; r.y = *(uint32_t*)&mb;
    }
    out[(((size_t)n * HOP + oy) * HOP + ox) * C4 + c] = r;
}

__global__ void fc_kernel(const float* __restrict__ in, const float* __restrict__ w,
                          const float* __restrict__ b, float* __restrict__ out,
                          int K_, int O_, int relu) {
    int idx = blockIdx.x * blockDim.x + threadIdx.x;
    if (idx >= NB * O_) return;
    int n = idx / O_, o = idx % O_;
    const float4* ip = (const float4*)(in + (size_t)n * K_);
    const float4* wp = (const float4*)(w + (size_t)o * K_);
    float s = b[o];
    int k4 = K_ >> 2;
#pragma unroll 4
    for (int k = 0; k < k4; ++k) {
        float4 a = ip[k], ww = wp[k];
        s = fmaf(a.x, ww.x, s); s = fmaf(a.y, ww.y, s);
        s = fmaf(a.z, ww.z, s); s = fmaf(a.w, ww.w, s);
    }
    if (relu) s = fmaxf(s, 0.f);
    out[idx] = s;
}

// ---------------- launch ----------------
extern "C" void kernel_launch(void* const* d_in, const int* in_sizes, int n_in,
                              void* d_out, int out_size) {
    const int*   X    = (const int*)  d_in[0];
    const int*   rmap = (const int*)  d_in[1];
    const float* emb  = (const float*)d_in[2];
    const float* cw0  = (const float*)d_in[3];
    const float* cb0  = (const float*)d_in[4];
    const float* cw1  = (const float*)d_in[5];
    const float* cb1  = (const float*)d_in[6];
    const float* cw2  = (const float*)d_in[7];
    const float* cb2  = (const float*)d_in[8];
    const float* fw0  = (const float*)d_in[9];
    const float* fb0  = (const float*)d_in[10];
    const float* fw1  = (const float*)d_in[11];
    const float* fb1  = (const float*)d_in[12];
    const float* fw2  = (const float*)d_in[13];
    const float* fb2  = (const float*)d_in[14];
    float* out = (float*)d_out;

    float *gapb, *f1, *f2;
    unsigned *grid, *c1, *p1, *c2, *p2, *wt1, *wt2, *wt3;
    cudaGetSymbolAddress((void**)&grid, g_grid);
    cudaGetSymbolAddress((void**)&c1,  g_c1);
    cudaGetSymbolAddress((void**)&p1,  g_p1);
    cudaGetSymbolAddress((void**)&c2,  g_c2);
    cudaGetSymbolAddress((void**)&p2,  g_p2);
    cudaGetSymbolAddress((void**)&gapb, g_gap);
    cudaGetSymbolAddress((void**)&f1,  g_f1);
    cudaGetSymbolAddress((void**)&f2,  g_f2);
    cudaGetSymbolAddress((void**)&wt1, g_wt1);
    cudaGetSymbolAddress((void**)&wt2, g_wt2);
    cudaGetSymbolAddress((void**)&wt3, g_wt3);

    const int SM1 = (16400 + 10240 + 416 + 26624) * 4;   // 214,720
    const int SM2 = (332 * 36 + 2 * 2048) * 4;           //  64,192
    const int SM3 = (30528 + 18432) * 4;                 // 195,840
    cudaFuncSetAttribute((const void*)conv1_kernel,
                         cudaFuncAttributeMaxDynamicSharedMemorySize, SM1);
    cudaFuncSetAttribute((const void*)conv2_kernel,
                         cudaFuncAttributeMaxDynamicSharedMemorySize, SM2);
    cudaFuncSetAttribute((const void*)conv3_kernel,
                         cudaFuncAttributeMaxDynamicSharedMemorySize, SM3);

    // zero grid (scatter accumulates into it)
    {
        int n4 = NB * 76 * 76 * 20 / 4;
        zero_kernel<<<(n4 + 255) / 256, 256>>>((float4*)grid, n4);
    }
    // fused weight transform
    wtrans_all_kernel<<<(210944 + 255) / 256, 256>>>(cw0, cw1, cw2, wt1, wt2, wt3);
    // scatter encode
    {
        int nt = NB * RNUM * 64;
        scatter_kernel<<<(nt + 255) / 256, 256>>>(X, rmap, emb, (__half2*)grid);
    }
    // conv1 + pool1
    conv1_kernel<<<dim3(11, 1, NB), 256, SM1>>>(grid, wt1, cb0, c1);
    {
        int nt = NB * 37 * 37 * 16;
        pool_half_kernel<64, 72, 35, 1><<<(nt + 255) / 256, 256>>>((const uint2*)c1, (uint2*)p1);
    }
    // conv2 (batch-flattened M) + pool2
    conv2_kernel<<<dim3(685, 2, 1), 256, SM2>>>(p1, wt2, cb1, c2);
    {
        int nt = NB * 19 * 19 * 32;
        pool_half_kernel<128, 35, 17, 1><<<(nt + 255) / 256, 256>>>((const uint2*)c2, (uint2*)p2);
    }
    // conv3 fused (both halves + pool + GAP)
    conv3_kernel<<<dim3(1, 4, NB), 256, SM3>>>(p2, wt3, cb2, gapb);
    // FC stack
    fc_kernel<<<(NB * 512 + 255) / 256, 256>>>(gapb, fw0, fb0, f1, 256, 512, 1);
    fc_kernel<<<(NB * 256 + 255) / 256, 256>>>(f1,   fw1, fb1, f2, 512, 256, 1);
    fc_kernel<<<(NB * 512 + 255) / 256, 256>>>(f2,   fw2, fb2, out, 256, 512, 0);
}

// round 16
// speedup vs baseline: 1.0088x; 1.0088x over previous
#include <cuda_runtime.h>
#include <cuda_fp16.h>
#include <stdint.h>

// ---------------- problem constants ----------------
#define NB   128
#define RNUM 300
#define EMB  32

// ---------------- buffers ----------------
__device__ unsigned g_grid[NB * 76 * 76 * 20];   // half2 words
__device__ unsigned g_c1 [NB * 72 * 72 * 32];    // conv1 out half2 (64ch)
__device__ unsigned g_p1 [NB * 37 * 37 * 32];    // pool1 half2 (pad1)
__device__ unsigned g_c2 [NB * 35 * 35 * 64];    // conv2 out half2 (128ch)
__device__ unsigned g_p2 [NB * 19 * 19 * 64];    // pool2 half2 (pad1)
__device__ float    g_c3 [NB * 17 * 17 * 256];   // conv3 partial (ci 0..63) fp32
__device__ float    g_gap[NB * 256];
__device__ float    g_f1 [NB * 512];
__device__ float    g_f2 [NB * 256];
__device__ unsigned g_wt1[ 26624];               // conv1 B
__device__ unsigned g_wt2[ 36864];               // [cob2][tap9][c16 4][nt8][64]
__device__ unsigned g_wt3[147456];               // [h2][cob8][kk9][c16 4][nt4][64]

// ---------------- helpers ----------------
__device__ __forceinline__ void mma_f16(float* d, const uint32_t* a, const uint32_t* b) {
    asm volatile(
        "mma.sync.aligned.m16n8k16.row.col.f32.f16.f16.f32 "
        "{%0,%1,%2,%3}, {%4,%5,%6,%7}, {%8,%9}, {%0,%1,%2,%3};"
        : "+f"(d[0]), "+f"(d[1]), "+f"(d[2]), "+f"(d[3])
        : "r"(a[0]), "r"(a[1]), "r"(a[2]), "r"(a[3]), "r"(b[0]), "r"(b[1]));
}
__device__ __forceinline__ void ldsm_x4(uint32_t* a, uint32_t addr) {
    asm volatile("ldmatrix.sync.aligned.m8n8.x4.shared.b16 {%0,%1,%2,%3}, [%4];"
        : "=r"(a[0]), "=r"(a[1]), "=r"(a[2]), "=r"(a[3]) : "r"(addr));
}
__device__ __forceinline__ uint32_t smem_u32(const void* p) {
    uint32_t a;
    asm("{ .reg .u64 t; cvta.to.shared.u64 t, %1; cvt.u32.u64 %0, t; }" : "=r"(a) : "l"(p));
    return a;
}
__device__ __forceinline__ void cp_async16_s(uint32_t saddr, const void* g) {
    asm volatile("cp.async.cg.shared.global [%0], [%1], 16;" :: "r"(saddr), "l"(g));
}
__device__ __forceinline__ void cp_async16_z(uint32_t saddr, const void* g, uint32_t srcsz) {
    asm volatile("cp.async.cg.shared.global [%0], [%1], 16, %2;"
                 :: "r"(saddr), "l"(g), "r"(srcsz));
}
__device__ __forceinline__ uint32_t f2h2(float a, float b) {
    __half2 h = __float22half2_rn(make_float2(a, b));
    return *(uint32_t*)&h;
}

// ---------------- zero fill ----------------
__global__ void zero_kernel(float4* __restrict__ p, int n4) {
    int i = blockIdx.x * blockDim.x + threadIdx.x;
    if (i < n4) p[i] = make_float4(0.f, 0.f, 0.f, 0.f);
}

// ---------------- scatter rooms into half grid (half2 atomics) --------------
__global__ void scatter_kernel(const int* __restrict__ X,
                               const int* __restrict__ rm,
                               const float* __restrict__ emb,
                               __half2* __restrict__ grid) {
    int idx = blockIdx.x * blockDim.x + threadIdx.x;
    if (idx >= NB * RNUM * 64) return;
    int cell = idx & 63;
    int r    = (idx >> 6) % RNUM;
    int n    = idx / (RNUM * 64);
    if (!rm[r * 64 + cell]) return;
    int cx = cell >> 3, cy = cell & 7;
    int px = X[(n * RNUM + r) * 2 + 0];
    int py = X[(n * RNUM + r) * 2 + 1];
    int Y = py + cy + 2, Xc = px + cx + 2;
    __half2* base = grid + (((size_t)n * 76 + Y) * 76 + Xc) * 20;
    const float* er = emb + r * EMB;
#pragma unroll
    for (int w = 0; w < 16; ++w)
        atomicAdd(base + w, __float22half2_rn(make_float2(er[2 * w], er[2 * w + 1])));
    atomicAdd(base + 16, __float22half2_rn(make_float2(1.f, 0.f)));
}

// ------- fused weight transform (all three convs, one launch) ---------------
__global__ void wtrans_all_kernel(const float* __restrict__ w0,
                                  const float* __restrict__ w1,
                                  const float* __restrict__ w2,
                                  unsigned* __restrict__ wt1,
                                  unsigned* __restrict__ wt2,
                                  unsigned* __restrict__ wt3) {
    int i = blockIdx.x * blockDim.x + threadIdx.x;
    if (i < 26624) {
        int which = i & 1;
        int lane  = (i >> 1) & 31;
        int ac = lane & 3, ar = lane >> 2;
        if (i < 25600) {
            int r  = i >> 6;
            int nt = r % 8;  r /= 8;
            int c16 = r % 2;
            int tap = r / 2;
            int kl  = c16 * 16 + ac * 2 + which * 8;
            int co  = nt * 8 + ar;
            float v0 = w0[((size_t)co * 33 + 1 + kl) * 25 + tap];
            float v1 = w0[((size_t)co * 33 + 2 + kl) * 25 + tap];
            wt1[i] = f2h2(v0, v1);
        } else {
            int j  = i - 25600;
            int r2 = j >> 6;
            int nt = r2 % 8;
            int g  = r2 / 8;
            int kl = g * 16 + ac * 2 + which * 8;
            int co = nt * 8 + ar;
            float v0 = (kl     < 25) ? w0[((size_t)co * 33) * 25 + kl]     : 0.f;
            float v1 = (kl + 1 < 25) ? w0[((size_t)co * 33) * 25 + kl + 1] : 0.f;
            wt1[i] = f2h2(v0, v1);
        }
    } else if (i < 26624 + 36864) {
        int j = i - 26624;
        int which = j & 1;
        int lane  = (j >> 1) & 31;
        int r     = j >> 6;
        int nt  = r % 8;  r /= 8;
        int c16 = r % 4;  r /= 4;
        int kk  = r % 9;
        int cob = r / 9;
        int ac = lane & 3, ar = lane >> 2;
        int ci0 = c16 * 16 + ac * 2 + which * 8;
        int co  = cob * 64 + nt * 8 + ar;
        float v0 = w1[((size_t)co * 64 + ci0)     * 9 + kk];
        float v1 = w1[((size_t)co * 64 + ci0 + 1) * 9 + kk];
        wt2[j] = f2h2(v0, v1);
    } else if (i < 26624 + 36864 + 147456) {
        int j = i - 26624 - 36864;
        int which = j & 1;
        int lane  = (j >> 1) & 31;
        int r     = j >> 6;
        int nt  = r % 4;  r /= 4;
        int c16 = r % 4;  r /= 4;
        int kk  = r % 9;  r /= 9;
        int cob = r % 8;
        int h   = r / 8;
        int ac = lane & 3, ar = lane >> 2;
        int ci0 = h * 64 + c16 * 16 + ac * 2 + which * 8;
        int co  = cob * 32 + nt * 8 + ar;
        float v0 = w2[((size_t)co * 128 + ci0)     * 9 + kk];
        float v1 = w2[((size_t)co * 128 + ci0 + 1) * 9 + kk];
        wt3[j] = f2h2(v0, v1);
    }
}

// ---------------- conv1: NCO=64, MT=4, NT=8, 256thr (measured best) ----------
__global__ void __launch_bounds__(256, 1)
conv1_kernel(const unsigned* __restrict__ in, const unsigned* __restrict__ wt,
             const float* __restrict__ bias, unsigned* __restrict__ out) {
    constexpr int MT = 4, NT = 8, NTHR = 256;
    constexpr int MPIX = 512;
    constexpr int W = 72, PAD = 2, Wp = 76, NPIX = 76 * 76;
    constexpr int HALO = PAD * Wp + PAD;              // 154
    constexpr int AWIN = MPIX + 2 * HALO;             // 820
    constexpr int ASTE = 20;
    constexpr int AEW  = AWIN * ASTE;                 // 16400
    constexpr int IMW  = MPIX * ASTE;                 // 10240
    constexpr int OCW  = 416;
    constexpr int BW   = 26624;

    extern __shared__ uint32_t sm[];
    uint32_t* sAe = sm;
    uint32_t* sIm = sm + AEW;
    __half*   sOc = (__half*)(sm + AEW + IMW);
    uint32_t* sB  = sm + AEW + IMW + OCW;

    const int tid  = threadIdx.x;
    const int warp = tid >> 5, lane = tid & 31;
    const int ar   = lane >> 2, ac = lane & 3;
    const int n    = blockIdx.z;
    const int p0   = HALO + blockIdx.x * MPIX;
    const int s0   = p0 - HALO;
    const int wrow = warp * (16 * MT);

    {
        uint32_t sBu = smem_u32(sB);
        for (int c = tid; c < BW / 4; c += NTHR)
            cp_async16_s(sBu + c * 16, wt + c * 4);
        const unsigned* inb = in + (size_t)n * NPIX * 20;
        uint32_t sAu = smem_u32(sAe);
        for (int e = tid; e < AWIN * 4; e += NTHR) {
            int row = e >> 2, c = e & 3;
            int pix = s0 + row;
            cp_async16_z(sAu + (uint32_t)((row * ASTE + c * 4) * 4),
                         inb + (size_t)pix * 20 + c * 4,
                         (pix < NPIX) ? 16u : 0u);
        }
        asm volatile("cp.async.commit_group;" ::: "memory");
    }
    {
        const unsigned* inw = in + (size_t)n * NPIX * 20;
        for (int row = tid; row < AWIN; row += NTHR) {
            int pix = s0 + row;
            uint32_t v = (pix < NPIX) ? inw[(size_t)pix * 20 + 16] : 0u;
            sOc[row] = *(__half*)&v;
        }
    }
    __syncthreads();
    {
        __half* imh = (__half*)sIm;
        for (int e = tid; e < MPIX * 16; e += NTHR) {
            int rr = e >> 4, w2 = e & 15;
            int k0 = 2 * w2, k1 = 2 * w2 + 1;
            __half h0 = __float2half(0.f), h1 = h0;
            if (k0 < 25) {
                int sh = (k0 / 5 - 2) * Wp + (k0 % 5) - 2;
                h0 = sOc[rr + HALO + sh];
            }
            if (k1 < 25) {
                int sh = (k1 / 5 - 2) * Wp + (k1 % 5) - 2;
                h1 = sOc[rr + HALO + sh];
            }
            imh[(rr * ASTE) * 2 + 2 * w2]     = h0;
            imh[(rr * ASTE) * 2 + 2 * w2 + 1] = h1;
        }
    }
    asm volatile("cp.async.wait_group 0;" ::: "memory");
    __syncthreads();

    float d[MT][NT][4];
#pragma unroll
    for (int mt = 0; mt < MT; ++mt)
#pragma unroll
        for (int nt = 0; nt < NT; ++nt)
#pragma unroll
            for (int q = 0; q < 4; ++q) d[mt][nt][q] = 0.f;

    const uint32_t a_off0 = smem_u32(sAe) +
        (uint32_t)(((HALO + wrow + (lane & 15)) * ASTE + ((lane >> 4) << 2)) * 4);
    const uint32_t i_off0 = smem_u32(sIm) +
        (uint32_t)(((wrow + (lane & 15)) * ASTE + ((lane >> 4) << 2)) * 4);

    for (int tap = 0; tap < 25; ++tap) {
        int shift = (tap / 5 - PAD) * Wp + (tap % 5) - PAD;
        uint32_t abase = a_off0 + (uint32_t)(shift * (ASTE * 4));
        const uint2* btap = (const uint2*)sB + (size_t)tap * 512 + lane;
#pragma unroll
        for (int c16 = 0; c16 < 2; ++c16) {
            uint2 bf[NT];
#pragma unroll
            for (int nt = 0; nt < NT; ++nt)
                bf[nt] = btap[(c16 * NT + nt) * 32];
#pragma unroll
            for (int mt = 0; mt < MT; ++mt) {
                uint32_t af[4];
                ldsm_x4(af, abase + (uint32_t)((mt * 16 * ASTE + c16 * 8) * 4));
#pragma unroll
                for (int nt = 0; nt < NT; ++nt)
                    mma_f16(d[mt][nt], af, (const uint32_t*)&bf[nt]);
            }
        }
    }
    {
        const uint2* btap = (const uint2*)(sB + 25600) + lane;
#pragma unroll
        for (int g = 0; g < 2; ++g) {
            uint2 bf[NT];
#pragma unroll
            for (int nt = 0; nt < NT; ++nt)
                bf[nt] = btap[(g * NT + nt) * 32];
#pragma unroll
            for (int mt = 0; mt < MT; ++mt) {
                uint32_t af[4];
                ldsm_x4(af, i_off0 + (uint32_t)((mt * 16 * ASTE + g * 8) * 4));
#pragma unroll
                for (int nt = 0; nt < NT; ++nt)
                    mma_f16(d[mt][nt], af, (const uint32_t*)&bf[nt]);
            }
        }
    }

    float2 bv[NT];
#pragma unroll
    for (int nt = 0; nt < NT; ++nt)
        bv[nt] = *(const float2*)(bias + nt * 8 + 2 * ac);
#pragma unroll
    for (int mt = 0; mt < MT; ++mt) {
#pragma unroll
        for (int half = 0; half < 2; ++half) {
            int p = p0 + wrow + mt * 16 + half * 8 + ar;
            int y = p / Wp - PAD, x = p % Wp - PAD;
            // pool1 reads rows/cols 0..70 only — skip dead row/col 71
            if (x >= 0 && x < 71 && y >= 0 && y < 71) {
                uint32_t* ob = out + (((size_t)n * W + y) * W + x) * 32 + ac;
#pragma unroll
                for (int nt = 0; nt < NT; ++nt) {
                    float vx = fmaxf(d[mt][nt][half * 2 + 0] + bv[nt].x, 0.f);
                    float vy = fmaxf(d[mt][nt][half * 2 + 1] + bv[nt].y, 0.f);
                    ob[nt * 4] = f2h2(vx, vy);
                }
            }
        }
    }
}

// ------ conv2: batch-flattened M, MT=2 NT=8, per-tap B stream, 2 blk/SM ------
__global__ void __launch_bounds__(256, 2)
conv2_kernel(const unsigned* __restrict__ in, const unsigned* __restrict__ wt,
             const float* __restrict__ bias, unsigned* __restrict__ out) {
    constexpr int NT = 8, MT = 2, NTHR = 256;
    constexpr int K = 3, H = 35, W = 35, PAD = 1;
    constexpr int CO_TOTAL = 128;
    constexpr int NC16 = 4, TAPS = 9;
    constexpr int MPIX = 256;
    constexpr int Wp = 37, IMG = 37 * 37;
    constexpr int TOT = NB * IMG;
    constexpr int HALO = PAD * Wp + PAD;             // 38
    constexpr int AWIN = MPIX + 2 * HALO;            // 332
    constexpr int AST2 = 36;
    constexpr int AWORDS = AWIN * AST2;
    constexpr int BSLOT = NC16 * NT * 64;            // 2048

    extern __shared__ uint32_t sm[];
    uint32_t* sA = sm;
    uint32_t* sB = sm + AWORDS;

    const int tid  = threadIdx.x;
    const int warp = tid >> 5, lane = tid & 31;
    const int ar   = lane >> 2, ac = lane & 3;
    const int cob  = blockIdx.y;
    const int co0  = cob * 64;
    const int p0   = HALO + blockIdx.x * MPIX;
    const int s0   = p0 - HALO;
    const int wrow = warp * (16 * MT);

    const unsigned* wtc = wt + (size_t)cob * (TAPS * BSLOT);
    const uint32_t sBu = smem_u32(sB);
#pragma unroll
    for (int pf = 0; pf < 2; ++pf) {
        const unsigned* src = wtc + (size_t)pf * BSLOT;
        for (int c = tid; c < BSLOT / 4; c += NTHR)
            cp_async16_s(sBu + (pf * BSLOT + c * 4) * 4, src + c * 4);
        asm volatile("cp.async.commit_group;" ::: "memory");
    }
    {
        const uint4* inb = (const uint4*)in;
        uint32_t sAu = smem_u32(sA);
        for (int e = tid; e < AWIN * 8; e += NTHR) {
            int row = e >> 3, c = e & 7;
            int pix = s0 + row;
            cp_async16_z(sAu + (uint32_t)((row * AST2 + c * 4) * 4),
                         inb + (size_t)pix * 8 + c,
                         (pix < TOT) ? 16u : 0u);
        }
        asm volatile("cp.async.commit_group;" ::: "memory");
    }
    asm volatile("cp.async.wait_group 0;" ::: "memory");
    __syncthreads();

    float d[MT][NT][4];
#pragma unroll
    for (int mt = 0; mt < MT; ++mt)
#pragma unroll
        for (int nt = 0; nt < NT; ++nt)
#pragma unroll
            for (int q = 0; q < 4; ++q) d[mt][nt][q] = 0.f;

    const uint32_t a_off0 = smem_u32(sA) +
        (uint32_t)(((HALO + wrow + (lane & 15)) * AST2 + ((lane >> 4) << 2)) * 4);

#pragma unroll 1
    for (int tap = 0; tap < TAPS; ++tap) {
        if (tap >= 2) {
            asm volatile("cp.async.wait_group 1;" ::: "memory");
            __syncthreads();
        }
        int shift = (tap / K - PAD) * Wp + (tap % K) - PAD;
        uint32_t abase = a_off0 + (uint32_t)(shift * (AST2 * 4));
        const uint2* btap = (const uint2*)(sB + (tap & 1) * BSLOT) + lane;
#pragma unroll
        for (int c16 = 0; c16 < NC16; ++c16) {
            uint2 bf[NT];
#pragma unroll
            for (int nt = 0; nt < NT; ++nt)
                bf[nt] = btap[(c16 * NT + nt) * 32];
#pragma unroll
            for (int mt = 0; mt < MT; ++mt) {
                uint32_t af[4];
                ldsm_x4(af, abase + (uint32_t)((mt * 16 * AST2 + c16 * 8) * 4));
#pragma unroll
                for (int nt = 0; nt < NT; ++nt)
                    mma_f16(d[mt][nt], af, (const uint32_t*)&bf[nt]);
            }
        }
        if (tap + 2 < TAPS) {
            __syncthreads();
            const unsigned* src = wtc + (size_t)(tap + 2) * BSLOT;
            uint32_t dst = sBu + (tap & 1) * BSLOT * 4;
            for (int c = tid; c < BSLOT / 4; c += NTHR)
                cp_async16_s(dst + c * 16, src + c * 4);
            asm volatile("cp.async.commit_group;" ::: "memory");
        }
    }

    float2 bv[NT];
#pragma unroll
    for (int nt = 0; nt < NT; ++nt)
        bv[nt] = *(const float2*)(bias + co0 + nt * 8 + 2 * ac);

#pragma unroll
    for (int mt = 0; mt < MT; ++mt) {
#pragma unroll
        for (int half = 0; half < 2; ++half) {
            int p = p0 + wrow + mt * 16 + half * 8 + ar;
            if (p < TOT) {
                int n = p / IMG, l = p % IMG;
                int y = l / Wp - PAD, x = l % Wp - PAD;
                if (x >= 0 && x < W && y >= 0 && y < H) {
                    size_t pix = ((size_t)n * H + y) * W + x;
                    uint32_t* ob = (uint32_t*)out + pix * (CO_TOTAL / 2) + co0 / 2 + ac;
#pragma unroll
                    for (int nt = 0; nt < NT; ++nt) {
                        float vx = fmaxf(d[mt][nt][half * 2 + 0] + bv[nt].x, 0.f);
                        float vy = fmaxf(d[mt][nt][half * 2 + 1] + bv[nt].y, 0.f);
                        ob[nt * 4] = f2h2(vx, vy);
                    }
                }
            }
        }
    }
}

// ---------------- conv3 pass1: NCO=32, MT=3, raw f32 store (2 blk/SM) --------
__global__ void __launch_bounds__(256, 2)
conv3a_kernel(const unsigned* __restrict__ in, const unsigned* __restrict__ wt,
              float* __restrict__ out) {
    constexpr int NCO = 32, NT = 4, MT = 3;
    constexpr int K = 3, H = 17, W = 17, PAD = 1;
    constexpr int CO_TOTAL = 256;
    constexpr int NC16 = 4, TAPS = 9;
    constexpr int MPIX = 8 * 16 * MT;                // 384
    constexpr int Wp = W + 2 * PAD;
    constexpr int NPIX = Wp * (H + 2 * PAD);         // 361
    constexpr int HALO = PAD * Wp + PAD;             // 20
    constexpr int AWIN = MPIX + 2 * HALO;            // 424
    constexpr int AST2 = 36;
    constexpr int AWORDS = AWIN * AST2;
    constexpr int BWORDS = TAPS * NC16 * NT * 64;    // 9216

    extern __shared__ uint32_t sm[];
    uint32_t* sA = sm;
    uint32_t* sB = sm + AWORDS;

    const int tid  = threadIdx.x;
    const int warp = tid >> 5, lane = tid & 31;
    const int ar   = lane >> 2, ac = lane & 3;
    const int n    = blockIdx.z;
    const int cob  = blockIdx.y;
    const int co0  = cob * NCO;
    const int p0   = HALO;
    const int wrow = warp * (16 * MT);

    {
        const unsigned* wsrc = wt + (size_t)cob * BWORDS;
        uint32_t sBu = smem_u32(sB);
        for (int c = tid; c < BWORDS / 4; c += 256)
            cp_async16_s(sBu + c * 16, wsrc + c * 4);
        const uint4* inb = (const uint4*)in + (size_t)n * NPIX * 16;
        uint32_t sAu = smem_u32(sA);
        for (int e = tid; e < AWIN * 8; e += 256) {
            int row = e >> 3, c = e & 7;
            cp_async16_z(sAu + (uint32_t)((row * AST2 + c * 4) * 4),
                         inb + (size_t)row * 16 + c,
                         (row < NPIX) ? 16u : 0u);
        }
        asm volatile("cp.async.commit_group;" ::: "memory");
    }
    asm volatile("cp.async.wait_group 0;" ::: "memory");
    __syncthreads();

    float d[MT][NT][4];
#pragma unroll
    for (int mt = 0; mt < MT; ++mt)
#pragma unroll
        for (int nt = 0; nt < NT; ++nt)
#pragma unroll
            for (int q = 0; q < 4; ++q) d[mt][nt][q] = 0.f;

    const uint32_t a_off0 = smem_u32(sA) +
        (uint32_t)(((HALO + wrow + (lane & 15)) * AST2 + ((lane >> 4) << 2)) * 4);

    for (int tap = 0; tap < TAPS; ++tap) {
        int shift = (tap / K - PAD) * Wp + (tap % K) - PAD;
        uint32_t abase = a_off0 + (uint32_t)(shift * (AST2 * 4));
        const uint2* btap = (const uint2*)sB + (size_t)tap * (NC16 * NT * 32) + lane;
#pragma unroll
        for (int c16 = 0; c16 < NC16; ++c16) {
            uint2 bf[NT];
#pragma unroll
            for (int nt = 0; nt < NT; ++nt)
                bf[nt] = btap[(c16 * NT + nt) * 32];
#pragma unroll
            for (int mt = 0; mt < MT; ++mt) {
                uint32_t af[4];
                ldsm_x4(af, abase + (uint32_t)((mt * 16 * AST2 + c16 * 8) * 4));
#pragma unroll
                for (int nt = 0; nt < NT; ++nt)
                    mma_f16(d[mt][nt], af, (const uint32_t*)&bf[nt]);
            }
        }
    }

#pragma unroll
    for (int mt = 0; mt < MT; ++mt) {
#pragma unroll
        for (int half = 0; half < 2; ++half) {
            int p = p0 + wrow + mt * 16 + half * 8 + ar;
            int y = p / Wp - PAD, x = p % Wp - PAD;
            if (x >= 0 && x < W && y < H) {
                size_t pix = ((size_t)n * H + y) * W + x;
                float* ob = out + pix * CO_TOTAL + co0 + 2 * ac;
#pragma unroll
                for (int nt = 0; nt < NT; ++nt) {
                    float2 v;
                    v.x = d[mt][nt][half * 2 + 0];
                    v.y = d[mt][nt][half * 2 + 1];
                    *(float2*)(ob + nt * 8) = v;
                }
            }
        }
    }
}

// ------- conv3 pass2: accum prev + bias + relu + pool3 + GAP (2 blk/SM) ------
__global__ void __launch_bounds__(256, 2)
conv3b_kernel(const unsigned* __restrict__ in, const unsigned* __restrict__ wt,
              const float* __restrict__ bias, const float* __restrict__ prev,
              float* __restrict__ gap) {
    constexpr int NCO = 32, NT = 4, MT = 3;
    constexpr int K = 3, H = 17, W = 17, PAD = 1;
    constexpr int CO_TOTAL = 256;
    constexpr int NC16 = 4, TAPS = 9;
    constexpr int MPIX = 8 * 16 * MT;
    constexpr int Wp = W + 2 * PAD;
    constexpr int NPIX = Wp * (H + 2 * PAD);
    constexpr int HALO = PAD * Wp + PAD;
    constexpr int AWIN = MPIX + 2 * HALO;
    constexpr int AST2 = 36;
    constexpr int AWORDS = AWIN * AST2;              // 15264
    constexpr int BWORDS = TAPS * NC16 * NT * 64;
    constexpr int OST = 33;

    extern __shared__ uint32_t sm[];
    uint32_t* sA = sm;
    uint32_t* sB = sm + AWORDS;
    float*    sOut  = (float*)sm;                    // overlay: [289][33]
    float*    sPart = (float*)(sm + AWORDS);         // overlay: [32][8]

    const int tid  = threadIdx.x;
    const int warp = tid >> 5, lane = tid & 31;
    const int ar   = lane >> 2, ac = lane & 3;
    const int n    = blockIdx.z;
    const int cob  = blockIdx.y;
    const int co0  = cob * NCO;
    const int p0   = HALO;
    const int wrow = warp * (16 * MT);

    {
        const unsigned* wsrc = wt + ((size_t)8 + cob) * BWORDS;   // h=1 half
        uint32_t sBu = smem_u32(sB);
        for (int c = tid; c < BWORDS / 4; c += 256)
            cp_async16_s(sBu + c * 16, wsrc + c * 4);
        const uint4* inb = (const uint4*)in + (size_t)n * NPIX * 16 + 8;  // ci 64..127
        uint32_t sAu = smem_u32(sA);
        for (int e = tid; e < AWIN * 8; e += 256) {
            int row = e >> 3, c = e & 7;
            cp_async16_z(sAu + (uint32_t)((row * AST2 + c * 4) * 4),
                         inb + (size_t)row * 16 + c,
                         (row < NPIX) ? 16u : 0u);
        }
        asm volatile("cp.async.commit_group;" ::: "memory");
    }
    asm volatile("cp.async.wait_group 0;" ::: "memory");
    __syncthreads();

    float d[MT][NT][4];
#pragma unroll
    for (int mt = 0; mt < MT; ++mt)
#pragma unroll
        for (int nt = 0; nt < NT; ++nt)
#pragma unroll
            for (int q = 0; q < 4; ++q) d[mt][nt][q] = 0.f;

    const uint32_t a_off0 = smem_u32(sA) +
        (uint32_t)(((HALO + wrow + (lane & 15)) * AST2 + ((lane >> 4) << 2)) * 4);

    for (int tap = 0; tap < TAPS; ++tap) {
        int shift = (tap / K - PAD) * Wp + (tap % K) - PAD;
        uint32_t abase = a_off0 + (uint32_t)(shift * (AST2 * 4));
        const uint2* btap = (const uint2*)sB + (size_t)tap * (NC16 * NT * 32) + lane;
#pragma unroll
        for (int c16 = 0; c16 < NC16; ++c16) {
            uint2 bf[NT];
#pragma unroll
            for (int nt = 0; nt < NT; ++nt)
                bf[nt] = btap[(c16 * NT + nt) * 32];
#pragma unroll
            for (int mt = 0; mt < MT; ++mt) {
                uint32_t af[4];
                ldsm_x4(af, abase + (uint32_t)((mt * 16 * AST2 + c16 * 8) * 4));
#pragma unroll
                for (int nt = 0; nt < NT; ++nt)
                    mma_f16(d[mt][nt], af, (const uint32_t*)&bf[nt]);
            }
        }
    }

    float2 bv[NT];
#pragma unroll
    for (int nt = 0; nt < NT; ++nt)
        bv[nt] = *(const float2*)(bias + co0 + nt * 8 + 2 * ac);

    __syncthreads();   // sA/sB reads done; overlay output tile

#pragma unroll
    for (int mt = 0; mt < MT; ++mt) {
#pragma unroll
        for (int half = 0; half < 2; ++half) {
            int p = p0 + wrow + mt * 16 + half * 8 + ar;
            int y = p / Wp - PAD, x = p % Wp - PAD;
            if (x >= 0 && x < W && y < H) {
                size_t pix = ((size_t)n * H + y) * W + x;
                const float* pb = prev + pix * CO_TOTAL + co0 + 2 * ac;
                float* so = sOut + (y * W + x) * OST + 2 * ac;
#pragma unroll
                for (int nt = 0; nt < NT; ++nt) {
                    float2 pv = *(const float2*)(pb + nt * 8);
                    so[nt * 8 + 0] = fmaxf(pv.x + d[mt][nt][half * 2 + 0] + bv[nt].x, 0.f);
                    so[nt * 8 + 1] = fmaxf(pv.y + d[mt][nt][half * 2 + 1] + bv[nt].y, 0.f);
                }
            }
        }
    }
    __syncthreads();

    {
        int c = tid >> 3, seg = tid & 7;
        float s = 0.f;
#pragma unroll
        for (int j = 0; j < 8; ++j) {
            int pp = seg * 8 + j;
            int oy = pp >> 3, ox = pp & 7;
            const float* b0 = sOut + ((2 * oy) * W + 2 * ox) * OST + c;
            float m = b0[0];
#pragma unroll
            for (int dy = 0; dy < 3; ++dy)
#pragma unroll
                for (int dx = 0; dx < 3; ++dx)
                    m = fmaxf(m, b0[(dy * W + dx) * OST]);
            s += m;
        }
        sPart[c * 8 + seg] = s;
    }
    __syncthreads();
    if (tid < 32) {
        float s = 0.f;
#pragma unroll
        for (int j = 0; j < 8; ++j) s += sPart[tid * 8 + j];
        gap[(size_t)n * 256 + co0 + tid] = s * (1.0f / 64.0f);
    }
}

// ---------------- pools (write own pad frame) / fc ----------------
template<int C, int HI, int HO, int P>
__global__ void pool_half_kernel(const uint2* __restrict__ in, uint2* __restrict__ out) {
    constexpr int C4 = C / 4, HOP = HO + 2 * P;
    int idx = blockIdx.x * blockDim.x + threadIdx.x;
    if (idx >= NB * HOP * HOP * C4) return;
    int c  = idx % C4;
    int ox = (idx / C4) % HOP;
    int oy = (idx / (C4 * HOP)) % HOP;
    int n  = idx / (C4 * HOP * HOP);
    uint2 r;
    if (ox < P || ox >= HO + P || oy < P || oy >= HO + P) {
        r = make_uint2(0u, 0u);
    } else {
        const uint2* p = in + (((size_t)n * HI + 2 * (oy - P)) * HI + 2 * (ox - P)) * C4 + c;
        uint2 m0 = p[0];
        __half2 ma = *(__half2*)&m0.x, mb = *(__half2*)&m0.y;
#pragma unroll
        for (int dy = 0; dy < 3; ++dy)
#pragma unroll
            for (int dx = 0; dx < 3; ++dx) {
                uint2 q = p[((size_t)dy * HI + dx) * C4];
                ma = __hmax2(ma, *(__half2*)&q.x);
                mb = __hmax2(mb, *(__half2*)&q.y);
            }
        r.x = *(uint32_t*)&ma; r.y = *(uint32_t*)&mb;
    }
    out[(((size_t)n * HOP + oy) * HOP + ox) * C4 + c] = r;
}

__global__ void fc_kernel(const float* __restrict__ in, const float* __restrict__ w,
                          const float* __restrict__ b, float* __restrict__ out,
                          int K_, int O_, int relu) {
    int idx = blockIdx.x * blockDim.x + threadIdx.x;
    if (idx >= NB * O_) return;
    int n = idx / O_, o = idx % O_;
    const float4* ip = (const float4*)(in + (size_t)n * K_);
    const float4* wp = (const float4*)(w + (size_t)o * K_);
    float s = b[o];
    int k4 = K_ >> 2;
#pragma unroll 4
    for (int k = 0; k < k4; ++k) {
        float4 a = ip[k], ww = wp[k];
        s = fmaf(a.x, ww.x, s); s = fmaf(a.y, ww.y, s);
        s = fmaf(a.z, ww.z, s); s = fmaf(a.w, ww.w, s);
    }
    if (relu) s = fmaxf(s, 0.f);
    out[idx] = s;
}

// ---------------- launch ----------------
extern "C" void kernel_launch(void* const* d_in, const int* in_sizes, int n_in,
                              void* d_out, int out_size) {
    const int*   X    = (const int*)  d_in[0];
    const int*   rmap = (const int*)  d_in[1];
    const float* emb  = (const float*)d_in[2];
    const float* cw0  = (const float*)d_in[3];
    const float* cb0  = (const float*)d_in[4];
    const float* cw1  = (const float*)d_in[5];
    const float* cb1  = (const float*)d_in[6];
    const float* cw2  = (const float*)d_in[7];
    const float* cb2  = (const float*)d_in[8];
    const float* fw0  = (const float*)d_in[9];
    const float* fb0  = (const float*)d_in[10];
    const float* fw1  = (const float*)d_in[11];
    const float* fb1  = (const float*)d_in[12];
    const float* fw2  = (const float*)d_in[13];
    const float* fb2  = (const float*)d_in[14];
    float* out = (float*)d_out;

    float *c3, *gapb, *f1, *f2;
    unsigned *grid, *c1, *p1, *c2, *p2, *wt1, *wt2, *wt3;
    cudaGetSymbolAddress((void**)&grid, g_grid);
    cudaGetSymbolAddress((void**)&c1,  g_c1);
    cudaGetSymbolAddress((void**)&p1,  g_p1);
    cudaGetSymbolAddress((void**)&c2,  g_c2);
    cudaGetSymbolAddress((void**)&p2,  g_p2);
    cudaGetSymbolAddress((void**)&c3,  g_c3);
    cudaGetSymbolAddress((void**)&gapb, g_gap);
    cudaGetSymbolAddress((void**)&f1,  g_f1);
    cudaGetSymbolAddress((void**)&f2,  g_f2);
    cudaGetSymbolAddress((void**)&wt1, g_wt1);
    cudaGetSymbolAddress((void**)&wt2, g_wt2);
    cudaGetSymbolAddress((void**)&wt3, g_wt3);

    const int SM1 = (16400 + 10240 + 416 + 26624) * 4;   // 214,720
    const int SM2 = (332 * 36 + 2 * 2048) * 4;           //  64,192
    const int SM3 = (424 * 36 + 9216) * 4;               //  97,920
    cudaFuncSetAttribute((const void*)conv1_kernel,
                         cudaFuncAttributeMaxDynamicSharedMemorySize, SM1);
    cudaFuncSetAttribute((const void*)conv2_kernel,
                         cudaFuncAttributeMaxDynamicSharedMemorySize, SM2);
    cudaFuncSetAttribute((const void*)conv3a_kernel,
                         cudaFuncAttributeMaxDynamicSharedMemorySize, SM3);
    cudaFuncSetAttribute((const void*)conv3b_kernel,
                         cudaFuncAttributeMaxDynamicSharedMemorySize, SM3);

    // zero grid (scatter accumulates into it)
    {
        int n4 = NB * 76 * 76 * 20 / 4;
        zero_kernel<<<(n4 + 255) / 256, 256>>>((float4*)grid, n4);
    }
    // fused weight transform
    wtrans_all_kernel<<<(210944 + 255) / 256, 256>>>(cw0, cw1, cw2, wt1, wt2, wt3);
    // scatter encode
    {
        int nt = NB * RNUM * 64;
        scatter_kernel<<<(nt + 255) / 256, 256>>>(X, rmap, emb, (__half2*)grid);
    }
    // conv1 + pool1
    conv1_kernel<<<dim3(11, 1, NB), 256, SM1>>>(grid, wt1, cb0, c1);
    {
        int nt = NB * 37 * 37 * 16;
        pool_half_kernel<64, 72, 35, 1><<<(nt + 255) / 256, 256>>>((const uint2*)c1, (uint2*)p1);
    }
    // conv2 (batch-flattened M) + pool2
    conv2_kernel<<<dim3(685, 2, 1), 256, SM2>>>(p1, wt2, cb1, c2);
    {
        int nt = NB * 19 * 19 * 32;
        pool_half_kernel<128, 35, 17, 1><<<(nt + 255) / 256, 256>>>((const uint2*)c2, (uint2*)p2);
    }
    // conv3: pass1 raw, pass2 fused accum+bias+relu+pool+GAP
    conv3a_kernel<<<dim3(1, 8, NB), 256, SM3>>>(p2, wt3, c3);
    conv3b_kernel<<<dim3(1, 8, NB), 256, SM3>>>(p2, wt3, cb2, c3, gapb);
    // FC stack
    fc_kernel<<<(NB * 512 + 255) / 256, 256>>>(gapb, fw0, fb0, f1, 256, 512, 1);
    fc_kernel<<<(NB * 256 + 255) / 256, 256>>>(f1,   fw1, fb1, f2, 512, 256, 1);
    fc_kernel<<<(NB * 512 + 255) / 256, 256>>>(f2,   fw2, fb2, out, 256, 512, 0);
}